// round 8
// baseline (speedup 1.0000x reference)
#include <cuda_runtime.h>
#include <cstdint>

// Problem shape (fixed by the reference)
#define T_STEPS 5
#define BB 32
#define CC 128
#define HW 1024                    // 32*32
#define NPT (BB * CC * HW)         // 4,194,304 elements per timestep
#define N4  (NPT / 4)              // 1,048,576 float4 per timestep
#define NTHR 1024                  // threads per CTA (one CTA per channel)
#define BATCH_F4 (CC * HW / 4)     // 32768 float4 per batch slice
#define JSTRIDE  (4 * BATCH_F4)    // 131072: float4 stride between j-iterations

static constexpr float V_TH    = 0.5f;
static constexpr float W_DEC   = 0.5f;
static constexpr float LOWER_C = 0.2f - 0.03f;   // 0.17
static constexpr float UPPER_C = 0.2f + 0.03f;   // 0.23
static constexpr float EMA0    = 0.17f;
static constexpr float INV_N   = 1.0f / 32768.0f; // 1/(B*H*W)

__device__ __forceinline__ float sigmoidf(float x) {
    return 1.0f / (1.0f + expf(-x));
}

// One CTA per channel; the whole recurrence (membrane carry, spike sums, EMA,
// inhibition weight) is channel-local -> no cross-CTA communication at all.
// Membrane carry: 8 float4 per thread, held in REGISTERS across all 5 steps
// (t- and j-loops fully unrolled). Each step front-batches all 16 LDG.128
// before any compute -> MLP_p1 = 16 per thread.
__global__ __launch_bounds__(NTHR, 1)
void lif_all(const float* __restrict__ xe,
             const float* __restrict__ xi,
             const float* __restrict__ alpha_raw,
             const float* __restrict__ beta_raw,
             float* __restrict__ out)
{
    __shared__ float s_wsum[NTHR / 32];
    __shared__ float s_bw;

    const int c    = blockIdx.x;               // channel
    const int tid  = threadIdx.x;
    const int lane = tid & 31;
    const int wid  = tid >> 5;

    const float alpha = 4.0f * sigmoidf(__ldg(alpha_raw));
    const float beta  = sigmoidf(__ldg(beta_raw));

    // Thread's base float4 index for j=0: batch (tid>>8), channel c, offset tid&255
    const int g0 = (tid >> 8) * BATCH_F4 + c * (HW / 4) + (tid & 255);

    const float4* xe4  = reinterpret_cast<const float4*>(xe);
    const float4* xi4  = reinterpret_cast<const float4*>(xi);
    float4*       out4 = reinterpret_cast<float4*>(out);

    float4 m[8];                               // membrane carry, register-resident
    float  ema = EMA0;                         // maintained by thread 0 only
    float  bw  = beta;                         // inhw starts at 0

    #pragma unroll
    for (int t = 0; t < T_STEPS; ++t) {
        const float4* xet = xe4  + (size_t)t * N4 + g0;
        const float4* xit = xi4  + (size_t)t * N4 + g0;
        float4*       st  = out4 + (size_t)t * N4 + g0;
        const bool last = (t == T_STEPS - 1);

        // Front-batch ALL loads for this step (16 back-to-back LDG.128)
        float4 e[8], v[8];
        #pragma unroll
        for (int j = 0; j < 8; ++j) e[j] = __ldcs(xet + j * JSTRIDE);
        #pragma unroll
        for (int j = 0; j < 8; ++j) v[j] = __ldcs(xit + j * JSTRIDE);

        float cnt = 0.0f;
        #pragma unroll
        for (int j = 0; j < 8; ++j) {
            float4 mm = (t == 0) ? make_float4(0.f, 0.f, 0.f, 0.f) : m[j];
            float4 s;

            mm.x = W_DEC * mm.x + e[j].x / (1.0f + alpha * v[j].x) - bw * v[j].x;
            s.x = (mm.x >= V_TH) ? 1.0f : 0.0f;  mm.x -= V_TH * s.x;
            mm.y = W_DEC * mm.y + e[j].y / (1.0f + alpha * v[j].y) - bw * v[j].y;
            s.y = (mm.y >= V_TH) ? 1.0f : 0.0f;  mm.y -= V_TH * s.y;
            mm.z = W_DEC * mm.z + e[j].z / (1.0f + alpha * v[j].z) - bw * v[j].z;
            s.z = (mm.z >= V_TH) ? 1.0f : 0.0f;  mm.z -= V_TH * s.z;
            mm.w = W_DEC * mm.w + e[j].w / (1.0f + alpha * v[j].w) - bw * v[j].w;
            s.w = (mm.w >= V_TH) ? 1.0f : 0.0f;  mm.w -= V_TH * s.w;

            __stcs(st + j * JSTRIDE, s);
            if (!last) {
                m[j] = mm;
                cnt += s.x + s.y + s.z + s.w;
            }
        }

        if (!last) {
            // Block reduction of the channel's spike count (integer-valued
            // floats < 2^24: exact in any order)
            #pragma unroll
            for (int off = 16; off > 0; off >>= 1)
                cnt += __shfl_down_sync(0xFFFFFFFFu, cnt, off);
            if (lane == 0) s_wsum[wid] = cnt;
            __syncthreads();
            if (wid == 0) {
                float s = s_wsum[lane];        // exactly 32 warps
                #pragma unroll
                for (int off = 16; off > 0; off >>= 1)
                    s += __shfl_down_sync(0xFFFFFFFFu, s, off);
                if (lane == 0) {
                    ema = 0.9f * ema + 0.1f * (s * INV_N);
                    const float inhw =
                        4.0f * (sigmoidf(LOWER_C - ema) - sigmoidf(ema - UPPER_C));
                    s_bw = beta * (1.0f - inhw);
                }
            }
            __syncthreads();
            bw = s_bw;
        }
    }
}

extern "C" void kernel_launch(void* const* d_in, const int* in_sizes, int n_in,
                              void* d_out, int out_size)
{
    const float* xe = (const float*)d_in[0];  // x_exc  [T,B,C,H,W]
    const float* xi = (const float*)d_in[1];  // x_inh  [T,B,C,H,W]
    const float* ar = (const float*)d_in[2];  // alpha_raw scalar
    const float* br = (const float*)d_in[3];  // beta_raw scalar
    float* out = (float*)d_out;               // spikes [T,B,C,H,W]

    lif_all<<<CC, NTHR>>>(xe, xi, ar, br, out);
}

// round 9
// speedup vs baseline: 1.1477x; 1.1477x over previous
#include <cuda_runtime.h>
#include <cstdint>

// Problem shape (fixed by the reference)
#define T_STEPS 5
#define BB 32
#define CC 128
#define HW 1024                    // 32*32
#define NPLANES (BB * CC)          // 4096 (b,c) planes
#define NPT (NPLANES * HW)         // 4,194,304 elements per timestep
#define N4  (NPT / 4)              // 1,048,576 float4 per timestep

#define NBLK 152                   // one CTA per SM (GB300: 152 SMs)
#define NTHR 1024
// Dynamic smem padded to force occupancy=1 (guarantees 1 CTA/SM spread AND
// residency of all 152 CTAs for the spin barrier). Max need: 27 planes * 4KB.
#define SMEM_BYTES (120 * 1024)

static constexpr float V_TH    = 0.5f;
static constexpr float W_DEC   = 0.5f;
static constexpr float LOWER_C = 0.2f - 0.03f;   // 0.17
static constexpr float UPPER_C = 0.2f + 0.03f;   // 0.23
static constexpr float EMA0    = 0.17f;
static constexpr float INV_N   = 1.0f / 32768.0f; // 1/(B*H*W)

// Cross-CTA state (device globals — no allocation allowed)
__device__ float    g_chsum[T_STEPS - 1][CC];  // per-step per-channel spike sums
__device__ unsigned g_bar;                     // grid barrier arrive counter

__device__ __forceinline__ float sigmoidf(float x) {
    return 1.0f / (1.0f + expf(-x));
}

__global__ void lif_init() {
    if (threadIdx.x == 0) g_bar = 0u;
    int i = threadIdx.x;
    if (i < (T_STEPS - 1) * CC) ((float*)g_chsum)[i] = 0.0f;
}

// 152 CTAs (one per SM), each owns a contiguous run of 26-27 (b,c) planes.
// Membrane carry in smem (thread-private slots). Per-channel spike sums go
// smem -> global atomics; a software grid barrier separates steps; each CTA
// then rebuilds bw[c] = beta*(1-inhw[c]) by replaying the EMA recurrence from
// the persisted per-step sums.
__global__ __launch_bounds__(NTHR, 1)
void lif_all(const float* __restrict__ xe,
             const float* __restrict__ xi,
             const float* __restrict__ alpha_raw,
             const float* __restrict__ beta_raw,
             float* __restrict__ out)
{
    extern __shared__ float4 s_mem[];      // membrane carry (<=6912 float4)
    __shared__ float s_bw[CC];
    __shared__ float s_cnt[CC];

    const int tid  = threadIdx.x;
    const int lane = tid & 31;

    // Contiguous plane partition: CTA k owns planes [k*4096/152,(k+1)*4096/152)
    const int p0 = (int)(((long long)blockIdx.x       * NPLANES) / NBLK);
    const int p1 = (int)(((long long)(blockIdx.x + 1) * NPLANES) / NBLK);
    const int f0    = p0 * (HW / 4);               // first float4 index (step-local)
    const int count = (p1 - p0) * (HW / 4);        // 6656 or 6912 float4

    const float alpha = 4.0f * sigmoidf(__ldg(alpha_raw));
    const float beta  = sigmoidf(__ldg(beta_raw));

    if (tid < CC) { s_bw[tid] = beta; s_cnt[tid] = 0.0f; }   // inhw starts 0
    __syncthreads();

    const float4* xe4  = reinterpret_cast<const float4*>(xe);
    const float4* xi4  = reinterpret_cast<const float4*>(xi);
    float4*       out4 = reinterpret_cast<float4*>(out);

    #pragma unroll
    for (int t = 0; t < T_STEPS; ++t) {
        const bool first = (t == 0);
        const bool last  = (t == T_STEPS - 1);
        const float4* xet = xe4  + (size_t)t * N4 + f0;
        const float4* xit = xi4  + (size_t)t * N4 + f0;
        float4*       st  = out4 + (size_t)t * N4 + f0;

        // 2-stage pipelined streaming loop over this CTA's contiguous range
        int i = tid;
        float4 e = __ldcs(xet + i);
        float4 v = __ldcs(xit + i);
        while (true) {
            const int inext = i + NTHR;
            const bool more = inext < count;
            float4 en, vn;
            if (more) {
                en = __ldcs(xet + inext);
                vn = __ldcs(xit + inext);
            }

            // Channel is warp-uniform: warp spans 32 consecutive float4 inside
            // a 256-float4 plane (f0 and i are 32-aligned per warp).
            const int c = ((f0 + i) >> 8) & (CC - 1);
            const float bw = s_bw[c];
            float4 m = first ? make_float4(0.f, 0.f, 0.f, 0.f) : s_mem[i];
            float4 s;

            m.x = W_DEC * m.x + e.x / (1.0f + alpha * v.x) - bw * v.x;
            s.x = (m.x >= V_TH) ? 1.0f : 0.0f;  m.x -= V_TH * s.x;
            m.y = W_DEC * m.y + e.y / (1.0f + alpha * v.y) - bw * v.y;
            s.y = (m.y >= V_TH) ? 1.0f : 0.0f;  m.y -= V_TH * s.y;
            m.z = W_DEC * m.z + e.z / (1.0f + alpha * v.z) - bw * v.z;
            s.z = (m.z >= V_TH) ? 1.0f : 0.0f;  m.z -= V_TH * s.z;
            m.w = W_DEC * m.w + e.w / (1.0f + alpha * v.w) - bw * v.w;
            s.w = (m.w >= V_TH) ? 1.0f : 0.0f;  m.w -= V_TH * s.w;

            __stcs(st + i, s);
            if (!last) {
                s_mem[i] = m;
                float cnt = s.x + s.y + s.z + s.w;   // integer-valued: exact
                #pragma unroll
                for (int off = 16; off > 0; off >>= 1)
                    cnt += __shfl_down_sync(0xFFFFFFFFu, cnt, off);
                if (lane == 0) atomicAdd(&s_cnt[c], cnt);
            }

            if (!more) break;
            i = inext;  e = en;  v = vn;
        }

        if (!last) {
            __syncthreads();
            // Flush this CTA's channel sums (only ~27 channels nonzero)
            if (tid < CC) {
                const float vsum = s_cnt[tid];
                if (vsum != 0.0f) atomicAdd(&g_chsum[t][tid], vsum);
                s_cnt[tid] = 0.0f;
            }
            // ---- grid barrier (publish atomics, arrive, spin) ----
            __syncthreads();
            if (tid == 0) {
                __threadfence();
                atomicAdd(&g_bar, 1u);
                const unsigned target = (unsigned)NBLK * (unsigned)(t + 1);
                while (*(volatile unsigned*)&g_bar < target) __nanosleep(64);
            }
            __syncthreads();
            // Rebuild bw table by replaying the EMA recurrence (t+1 steps)
            if (tid < CC) {
                float e2 = EMA0;
                for (int k = 0; k <= t; ++k)
                    e2 = 0.9f * e2 + 0.1f * (__ldcg(&g_chsum[k][tid]) * INV_N);
                const float inhw =
                    4.0f * (sigmoidf(LOWER_C - e2) - sigmoidf(e2 - UPPER_C));
                s_bw[tid] = beta * (1.0f - inhw);
            }
            __syncthreads();
        }
    }
}

extern "C" void kernel_launch(void* const* d_in, const int* in_sizes, int n_in,
                              void* d_out, int out_size)
{
    const float* xe = (const float*)d_in[0];  // x_exc  [T,B,C,H,W]
    const float* xi = (const float*)d_in[1];  // x_inh  [T,B,C,H,W]
    const float* ar = (const float*)d_in[2];  // alpha_raw scalar
    const float* br = (const float*)d_in[3];  // beta_raw scalar
    float* out = (float*)d_out;               // spikes [T,B,C,H,W]

    static bool attr_set = false;
    if (!attr_set) {
        cudaFuncSetAttribute(lif_all, cudaFuncAttributeMaxDynamicSharedMemorySize,
                             SMEM_BYTES);
        attr_set = true;
    }
    lif_init<<<1, (T_STEPS - 1) * CC>>>();
    lif_all<<<NBLK, NTHR, SMEM_BYTES>>>(xe, xi, ar, br, out);
}

// round 10
// speedup vs baseline: 1.4752x; 1.2854x over previous
#include <cuda_runtime.h>
#include <cstdint>

// Problem shape (fixed by the reference)
#define T_STEPS 5
#define BB 32
#define CC 128
#define HW 1024                    // 32*32
#define NPT (BB * CC * HW)         // 4,194,304 elements per timestep
#define N4  (NPT / 4)              // 1,048,576 float4 per timestep
#define NTHR 1024                  // threads per CTA (one CTA per channel)
#define BATCH_F4 (CC * HW / 4)     // 32768 float4 per batch slice
#define JSTRIDE  (4 * BATCH_F4)    // 131072: float4 stride between j-iterations
#define SMEM_BYTES (BB * HW * sizeof(float))   // 131072 B membrane carry

static constexpr float V_TH    = 0.5f;
static constexpr float W_DEC   = 0.5f;
static constexpr float LOWER_C = 0.2f - 0.03f;   // 0.17
static constexpr float UPPER_C = 0.2f + 0.03f;   // 0.23
static constexpr float EMA0    = 0.17f;
static constexpr float INV_N   = 1.0f / 32768.0f; // 1/(B*H*W)

__device__ __forceinline__ float sigmoidf(float x) {
    return 1.0f / (1.0f + expf(-x));
}

// One timestep for one channel (8 unrolled iterations x 1024 threads x float4
// = the channel's 32 planes). mem carry in SMEM (thread-private slots).
// 3-stage load pipeline: e/v loads issued TWO iterations ahead (ring of 3
// register buffers -> 4 LDG.128 in flight per thread).
template <bool FIRST, bool LAST>
__device__ __forceinline__ void do_step(
    const float4* __restrict__ xet, const float4* __restrict__ xit,
    float4* __restrict__ st, float4* __restrict__ s_mem,
    int g0, int tid, float alpha, float bw, float* cnt_out)
{
    float cnt = 0.0f;
    float4 e[3], v[3];

    // Prologue: fill two stages
    e[0] = __ldcs(xet + g0);
    v[0] = __ldcs(xit + g0);
    e[1] = __ldcs(xet + g0 + JSTRIDE);
    v[1] = __ldcs(xit + g0 + JSTRIDE);

    #pragma unroll
    for (int j = 0; j < 8; ++j) {
        // Issue loads two iterations ahead
        if (j < 6) {
            e[(j + 2) % 3] = __ldcs(xet + g0 + (j + 2) * JSTRIDE);
            v[(j + 2) % 3] = __ldcs(xit + g0 + (j + 2) * JSTRIDE);
        }

        float4 m;
        if (FIRST) m = make_float4(0.f, 0.f, 0.f, 0.f);
        else       m = s_mem[j * NTHR + tid];

        const float4 ec = e[j % 3];
        const float4 vc = v[j % 3];
        float4 s;

        m.x = W_DEC * m.x + ec.x / (1.0f + alpha * vc.x) - bw * vc.x;
        s.x = (m.x >= V_TH) ? 1.0f : 0.0f;  m.x -= V_TH * s.x;
        m.y = W_DEC * m.y + ec.y / (1.0f + alpha * vc.y) - bw * vc.y;
        s.y = (m.y >= V_TH) ? 1.0f : 0.0f;  m.y -= V_TH * s.y;
        m.z = W_DEC * m.z + ec.z / (1.0f + alpha * vc.z) - bw * vc.z;
        s.z = (m.z >= V_TH) ? 1.0f : 0.0f;  m.z -= V_TH * s.z;
        m.w = W_DEC * m.w + ec.w / (1.0f + alpha * vc.w) - bw * vc.w;
        s.w = (m.w >= V_TH) ? 1.0f : 0.0f;  m.w -= V_TH * s.w;

        __stcs(st + g0 + j * JSTRIDE, s);
        if (!LAST) {
            s_mem[j * NTHR + tid] = m;
            cnt += s.x + s.y + s.z + s.w;
        }
    }
    *cnt_out = cnt;
}

// One CTA per channel. The whole recurrence (mem carry, spike sums, EMA,
// inhibition weight) is channel-local, so no cross-CTA communication exists.
__global__ __launch_bounds__(NTHR, 1)
void lif_all(const float* __restrict__ xe,
             const float* __restrict__ xi,
             const float* __restrict__ alpha_raw,
             const float* __restrict__ beta_raw,
             float* __restrict__ out)
{
    extern __shared__ float4 s_mem[];          // 131 KB membrane carry
    __shared__ float s_wsum[NTHR / 32];
    __shared__ float s_bw;

    const int c    = blockIdx.x;               // channel
    const int tid  = threadIdx.x;
    const int lane = tid & 31;
    const int wid  = tid >> 5;

    const float alpha = 4.0f * sigmoidf(__ldg(alpha_raw));
    const float beta  = sigmoidf(__ldg(beta_raw));

    // Thread's base float4 index for j=0: batch (tid>>8), channel c, offset tid&255
    const int g0 = (tid >> 8) * BATCH_F4 + c * (HW / 4) + (tid & 255);

    const float4* xe4  = reinterpret_cast<const float4*>(xe);
    const float4* xi4  = reinterpret_cast<const float4*>(xi);
    float4*       out4 = reinterpret_cast<float4*>(out);

    float ema = EMA0;                          // maintained by thread 0 only
    float bw  = beta;                          // inhw starts at 0

    #pragma unroll
    for (int t = 0; t < T_STEPS; ++t) {
        const float4* xet = xe4  + (size_t)t * N4;
        const float4* xit = xi4  + (size_t)t * N4;
        float4*       st  = out4 + (size_t)t * N4;

        float cnt;
        if (t == 0)
            do_step<true, false>(xet, xit, st, s_mem, g0, tid, alpha, bw, &cnt);
        else if (t == T_STEPS - 1)
            do_step<false, true>(xet, xit, st, s_mem, g0, tid, alpha, bw, &cnt);
        else
            do_step<false, false>(xet, xit, st, s_mem, g0, tid, alpha, bw, &cnt);

        if (t < T_STEPS - 1) {
            // Block reduction of this channel's spike count (integer-valued
            // floats < 2^24: exact regardless of order)
            #pragma unroll
            for (int off = 16; off > 0; off >>= 1)
                cnt += __shfl_down_sync(0xFFFFFFFFu, cnt, off);
            if (lane == 0) s_wsum[wid] = cnt;
            __syncthreads();
            if (wid == 0) {
                float v = s_wsum[lane];        // exactly 32 warps
                #pragma unroll
                for (int off = 16; off > 0; off >>= 1)
                    v += __shfl_down_sync(0xFFFFFFFFu, v, off);
                if (lane == 0) {
                    ema = 0.9f * ema + 0.1f * (v * INV_N);
                    const float inhw =
                        4.0f * (sigmoidf(LOWER_C - ema) - sigmoidf(ema - UPPER_C));
                    s_bw = beta * (1.0f - inhw);
                }
            }
            __syncthreads();
            bw = s_bw;
        }
    }
}

extern "C" void kernel_launch(void* const* d_in, const int* in_sizes, int n_in,
                              void* d_out, int out_size)
{
    const float* xe = (const float*)d_in[0];  // x_exc  [T,B,C,H,W]
    const float* xi = (const float*)d_in[1];  // x_inh  [T,B,C,H,W]
    const float* ar = (const float*)d_in[2];  // alpha_raw scalar
    const float* br = (const float*)d_in[3];  // beta_raw scalar
    float* out = (float*)d_out;               // spikes [T,B,C,H,W]

    static bool attr_set = false;
    if (!attr_set) {
        cudaFuncSetAttribute(lif_all, cudaFuncAttributeMaxDynamicSharedMemorySize,
                             SMEM_BYTES);
        attr_set = true;
    }
    lif_all<<<CC, NTHR, SMEM_BYTES>>>(xe, xi, ar, br, out);
}

// round 11
// speedup vs baseline: 1.5544x; 1.0537x over previous
#include <cuda_runtime.h>
#include <cstdint>

// Problem shape (fixed by the reference)
#define T_STEPS 5
#define BB 32
#define CC 128
#define HW 1024                    // 32*32
#define NPT (BB * CC * HW)         // 4,194,304 elements per timestep
#define N4  (NPT / 4)              // 1,048,576 float4 per timestep
#define NTHR 1024                  // threads per CTA (one CTA per channel)
#define BATCH_F4 (CC * HW / 4)     // 32768 float4 per batch slice
#define JSTRIDE  (4 * BATCH_F4)    // 131072: float4 stride between j-iterations
#define SMEM_BYTES (BB * HW * sizeof(float))   // 131072 B membrane carry
#define KTOT (T_STEPS * 8)         // 40 flat iterations

static constexpr float V_TH    = 0.5f;
static constexpr float W_DEC   = 0.5f;
static constexpr float LOWER_C = 0.2f - 0.03f;   // 0.17
static constexpr float UPPER_C = 0.2f + 0.03f;   // 0.23
static constexpr float EMA0    = 0.17f;
static constexpr float INV_N   = 1.0f / 32768.0f; // 1/(B*H*W)

__device__ __forceinline__ float sigmoidf(float x) {
    return 1.0f / (1.0f + expf(-x));
}

// One CTA per channel; whole recurrence is channel-local (no cross-CTA comm).
// Flat 40-iteration stream (5 steps x 8 j), fully unrolled, with a 3-slot
// load ring carried ACROSS step boundaries: next step's first loads are
// issued before this step's reduction barrier, so the EMA/sync window runs
// with loads already in flight (no inter-step memory bubble).
__global__ __launch_bounds__(NTHR, 1)
void lif_all(const float* __restrict__ xe,
             const float* __restrict__ xi,
             const float* __restrict__ alpha_raw,
             const float* __restrict__ beta_raw,
             float* __restrict__ out)
{
    extern __shared__ float4 s_mem[];          // 131 KB membrane carry
    __shared__ float s_wsum[NTHR / 32];
    __shared__ float s_bw;

    const int c    = blockIdx.x;               // channel
    const int tid  = threadIdx.x;
    const int lane = tid & 31;
    const int wid  = tid >> 5;

    const float alpha = 4.0f * sigmoidf(__ldg(alpha_raw));
    const float beta  = sigmoidf(__ldg(beta_raw));

    // Thread's base float4 index for j=0: batch (tid>>8), channel c, offset tid&255
    const int g0 = (tid >> 8) * BATCH_F4 + c * (HW / 4) + (tid & 255);

    const float4* xe4  = reinterpret_cast<const float4*>(xe) + g0;
    const float4* xi4  = reinterpret_cast<const float4*>(xi) + g0;
    float4*       out4 = reinterpret_cast<float4*>(out)      + g0;

    float ema = EMA0;                          // maintained by (wid0,lane0) only
    float bw  = beta;                          // inhw starts at 0
    float cnt = 0.0f;

    float4 er[3], vr[3];
    // Prologue: loads for k=0,1
    er[0] = __ldcs(xe4);                 vr[0] = __ldcs(xi4);
    er[1] = __ldcs(xe4 + JSTRIDE);       vr[1] = __ldcs(xi4 + JSTRIDE);

    #pragma unroll
    for (int k = 0; k < KTOT; ++k) {
        const int t = k >> 3;                  // step (compile-time)
        const int j = k & 7;                   // plane-group within step

        // Issue loads two iterations ahead (crosses step boundaries)
        if (k + 2 < KTOT) {
            const int t2 = (k + 2) >> 3, j2 = (k + 2) & 7;
            const size_t off = (size_t)t2 * N4 + (size_t)j2 * JSTRIDE;
            er[(k + 2) % 3] = __ldcs(xe4 + off);
            vr[(k + 2) % 3] = __ldcs(xi4 + off);
        }

        const float4 e = er[k % 3];
        const float4 v = vr[k % 3];
        float4 m = (t == 0) ? make_float4(0.f, 0.f, 0.f, 0.f)
                            : s_mem[j * NTHR + tid];
        float4 s;

        m.x = W_DEC * m.x + e.x / (1.0f + alpha * v.x) - bw * v.x;
        s.x = (m.x >= V_TH) ? 1.0f : 0.0f;  m.x -= V_TH * s.x;
        m.y = W_DEC * m.y + e.y / (1.0f + alpha * v.y) - bw * v.y;
        s.y = (m.y >= V_TH) ? 1.0f : 0.0f;  m.y -= V_TH * s.y;
        m.z = W_DEC * m.z + e.z / (1.0f + alpha * v.z) - bw * v.z;
        s.z = (m.z >= V_TH) ? 1.0f : 0.0f;  m.z -= V_TH * s.z;
        m.w = W_DEC * m.w + e.w / (1.0f + alpha * v.w) - bw * v.w;
        s.w = (m.w >= V_TH) ? 1.0f : 0.0f;  m.w -= V_TH * s.w;

        __stcs(out4 + (size_t)t * N4 + (size_t)j * JSTRIDE, s);

        if (t < T_STEPS - 1) {
            s_mem[j * NTHR + tid] = m;
            cnt += s.x + s.y + s.z + s.w;
        }

        // Step boundary: reduce this channel's spike count, update bw.
        // Next step's first loads are ALREADY in flight (issued at k-1, k).
        if (j == 7 && t < T_STEPS - 1) {
            float r = cnt;                     // integer-valued: exact any order
            #pragma unroll
            for (int off = 16; off > 0; off >>= 1)
                r += __shfl_down_sync(0xFFFFFFFFu, r, off);
            if (lane == 0) s_wsum[wid] = r;
            __syncthreads();
            if (wid == 0) {
                float x = s_wsum[lane];        // exactly 32 warps
                #pragma unroll
                for (int off = 16; off > 0; off >>= 1)
                    x += __shfl_down_sync(0xFFFFFFFFu, x, off);
                if (lane == 0) {
                    ema = 0.9f * ema + 0.1f * (x * INV_N);
                    const float inhw =
                        4.0f * (sigmoidf(LOWER_C - ema) - sigmoidf(ema - UPPER_C));
                    s_bw = beta * (1.0f - inhw);
                }
            }
            __syncthreads();
            bw  = s_bw;
            cnt = 0.0f;
        }
    }
}

extern "C" void kernel_launch(void* const* d_in, const int* in_sizes, int n_in,
                              void* d_out, int out_size)
{
    const float* xe = (const float*)d_in[0];  // x_exc  [T,B,C,H,W]
    const float* xi = (const float*)d_in[1];  // x_inh  [T,B,C,H,W]
    const float* ar = (const float*)d_in[2];  // alpha_raw scalar
    const float* br = (const float*)d_in[3];  // beta_raw scalar
    float* out = (float*)d_out;               // spikes [T,B,C,H,W]

    static bool attr_set = false;
    if (!attr_set) {
        cudaFuncSetAttribute(lif_all, cudaFuncAttributeMaxDynamicSharedMemorySize,
                             SMEM_BYTES);
        attr_set = true;
    }
    lif_all<<<CC, NTHR, SMEM_BYTES>>>(xe, xi, ar, br, out);
}